// round 14
// baseline (speedup 1.0000x reference)
#include <cuda_runtime.h>
#include <cuda.h>
#include <cuda_fp16.h>
#include <cstdint>
#include <cstring>

// ---------------- problem constants ----------------
#define TOKENS 8192
#define IN_F   4096
#define OUT_F  11008

// ---------------- GEMM tiling ----------------
constexpr int TILE_M = 256;            // CTA M
constexpr int TILE_N = 128;            // CTA N
constexpr int KC     = 128;            // K elems per stage (2 x 64-col SW128 chunks)
constexpr int NKIT   = IN_F / KC;      // 32
constexpr int S      = 2;              // pipeline stages (ping-pong)

constexpr int NT_M   = TOKENS / TILE_M;   // 32 (power of two)
constexpr int NT_N   = OUT_F / TILE_N;    // 86
constexpr int NTILES = NT_M * NT_N;       // 2752

constexpr int NTHREADS = 512;          // 16 warps: 4(warp_m) x 4(warp_n), tile 64x32

// ---------------- SMEM layout ----------------
constexpr int SMEM_TILES   = 1024;                 // 1024-aligned for SW128
constexpr int A_CHUNK      = TILE_M * 128;         // 32768 (64 k-cols)
constexpr int B_CHUNK      = TILE_N * 128;         // 16384
constexpr int A_BYTES      = 2 * A_CHUNK;          // 65536
constexpr int B_BYTES      = 2 * B_CHUNK;          // 32768
constexpr int STAGE_BYTES  = A_BYTES + B_BYTES;    // 98304
constexpr int SMEM_TOTAL   = SMEM_TILES + S * STAGE_BYTES;  // 197632

// ---------------- scratch (fp16 copies) + work-steal counter ----------------
__device__ __align__(1024) __half g_x16[(size_t)TOKENS * IN_F];
__device__ __align__(1024) __half g_w16[(size_t)OUT_F * IN_F];
__device__ int g_ticket;

// ---------------- PTX helpers ----------------
__device__ __forceinline__ uint32_t smem_u32(const void* p) {
    uint32_t a;
    asm("{ .reg .u64 t; cvta.to.shared.u64 t, %1; cvt.u32.u64 %0, t; }" : "=r"(a) : "l"(p));
    return a;
}

#define MBAR_INIT(a, c) \
    asm volatile("mbarrier.init.shared.b64 [%0], %1;" :: "r"(a), "r"((uint32_t)(c)) : "memory")

#define MBAR_EXPECT_TX(a, b) \
    asm volatile("mbarrier.arrive.expect_tx.shared.b64 _, [%0], %1;" :: "r"(a), "r"((uint32_t)(b)) : "memory")

#define MBAR_ARRIVE(a) \
    asm volatile("mbarrier.arrive.shared.b64 _, [%0];" :: "r"(a) : "memory")

#define MBAR_WAIT(a, ph) do {                                                          \
    uint32_t _m = (a); uint32_t _p = (uint32_t)(ph); uint32_t _d;                      \
    asm volatile("{\n .reg .pred p;\n"                                                 \
                 " mbarrier.try_wait.parity.acquire.cta.shared::cta.b64 p, [%1], %2;\n" \
                 " selp.b32 %0, 1, 0, p;\n}" : "=r"(_d) : "r"(_m), "r"(_p) : "memory"); \
    if (!_d) {                                                                         \
        asm volatile("{\n .reg .pred P1;\n"                                            \
                     "WL_%=:\n"                                                         \
                     " mbarrier.try_wait.parity.acquire.cta.shared::cta.b64 P1, [%0], %1, 0x989680;\n" \
                     " @P1 bra.uni WD_%=;\n bra.uni WL_%=;\nWD_%=:\n}"                  \
                     :: "r"(_m), "r"(_p) : "memory");                                   \
    }                                                                                   \
} while (0)

__device__ __forceinline__ void tma2d(uint32_t dst, const CUtensorMap* m, int cx, int cy,
                                      uint32_t bar) {
    asm volatile(
        "cp.async.bulk.tensor.2d.shared::cta.global.tile.mbarrier::complete_tx::bytes "
        "[%0], [%1, {%2, %3}], [%4];"
        :: "r"(dst), "l"(m), "r"(cx), "r"(cy), "r"(bar) : "memory");
}

__device__ __forceinline__ void ldsm4(uint32_t* r, uint32_t addr) {
    asm volatile("ldmatrix.sync.aligned.m8n8.x4.shared.b16 {%0,%1,%2,%3}, [%4];"
                 : "=r"(r[0]), "=r"(r[1]), "=r"(r[2]), "=r"(r[3]) : "r"(addr));
}

__device__ __forceinline__ void mma16816(float* c, const uint32_t* a, const uint32_t* b) {
    asm volatile(
        "mma.sync.aligned.m16n8k16.row.col.f32.f16.f16.f32 "
        "{%0,%1,%2,%3}, {%4,%5,%6,%7}, {%8,%9}, {%0,%1,%2,%3};"
        : "+f"(c[0]), "+f"(c[1]), "+f"(c[2]), "+f"(c[3])
        : "r"(a[0]), "r"(a[1]), "r"(a[2]), "r"(a[3]), "r"(b[0]), "r"(b[1]));
}

// SW128: XOR 16B-column index with (row & 7)
__device__ __forceinline__ uint32_t sw128(uint32_t off) {
    return off ^ ((off >> 3) & 0x70);
}

// ---------------- fused conversion kernel (single launch) ----------------
// x: fp32 -> fp16 ; w: int32 (harness-upcast int8) -> fp16 ; resets ticket
__global__ void __launch_bounds__(256) cvt_all_kernel(const float4* __restrict__ x,
                                                      uint2* __restrict__ ox, int n4x,
                                                      const int4* __restrict__ w,
                                                      uint2* __restrict__ ow, int n4w,
                                                      int ticket0) {
    if (blockIdx.x == 0 && threadIdx.x == 0) g_ticket = ticket0;
    int i = blockIdx.x * blockDim.x + threadIdx.x;
    if (i < n4x) {
        float4 v = x[i];
        __half2 a = __floats2half2_rn(v.x, v.y);
        __half2 b = __floats2half2_rn(v.z, v.w);
        uint2 u;
        memcpy(&u.x, &a, 4);
        memcpy(&u.y, &b, 4);
        ox[i] = u;
    } else {
        int j = i - n4x;
        if (j < n4w) {
            int4 v = w[j];
            __half2 a = __floats2half2_rn((float)v.x, (float)v.y);
            __half2 b = __floats2half2_rn((float)v.z, (float)v.w);
            uint2 u;
            memcpy(&u.x, &a, 4);
            memcpy(&u.y, &b, 4);
            ow[j] = u;
        }
    }
}

// ---------------- main GEMM kernel (persistent + work stealing, 16 warps) ----
__global__ void __launch_bounds__(NTHREADS, 1)
qlin_gemm_kernel(const __grid_constant__ CUtensorMap tmA,
                 const __grid_constant__ CUtensorMap tmB,
                 const float* __restrict__ scales,
                 const float* __restrict__ bias,
                 float* __restrict__ out) {
    extern __shared__ __align__(1024) char smem[];
    const uint32_t sb = smem_u32(smem);
    const int tid  = threadIdx.x;
    const int wid  = tid >> 5;
    const int lane = tid & 31;
    const int warp_m = wid >> 2;     // 0..3  (64 rows each)
    const int warp_n = wid & 3;      // 0..3  (32 cols each)

    const int bid = blockIdx.x;

#define FULL_BAR(s)  (sb + (s) * 16)
#define EMPTY_BAR(s) (sb + (s) * 16 + 8)
#define A_OFF(s)     (SMEM_TILES + (s) * STAGE_BYTES)
#define B_OFF(s)     (A_OFF(s) + A_BYTES)

    int* s_next = reinterpret_cast<int*>(smem + 64);

    if (tid == 0) {
        #pragma unroll
        for (int s = 0; s < S; s++) {
            MBAR_INIT(FULL_BAR(s), 1);
            MBAR_INIT(EMPTY_BAR(s), 16);   // one arrive per warp
        }
        *s_next = NTILES;  // sentinel until first fetch
    }
    __syncthreads();

    // prologue: issue stage 0 of first (static) tile
    if (tid == 0) {
        int m0 = (bid & (NT_M - 1)) * TILE_M;
        int n0 = (bid >> 5) * TILE_N;
        MBAR_EXPECT_TX(FULL_BAR(0), STAGE_BYTES);
        tma2d(sb + A_OFF(0),           &tmA, 0,  m0, FULL_BAR(0));
        tma2d(sb + A_OFF(0) + A_CHUNK, &tmA, 64, m0, FULL_BAR(0));
        tma2d(sb + B_OFF(0),           &tmB, 0,  n0, FULL_BAR(0));
        tma2d(sb + B_OFF(0) + B_CHUNK, &tmB, 64, n0, FULL_BAR(0));
    }

    // fragment base byte offsets (tile-invariant; chunk-relative, before swizzle)
    uint32_t aRow[4], bRow[2];
    #pragma unroll
    for (int mt = 0; mt < 4; mt++)
        aRow[mt] = (uint32_t)(warp_m * 64 + mt * 16 + (lane & 15)) * 128 +
                   ((lane >> 4) << 4);
    #pragma unroll
    for (int n2 = 0; n2 < 2; n2++)
        bRow[n2] = (uint32_t)(warp_n * 32 + n2 * 16 + (lane & 7) + ((lane >> 4) << 3)) * 128 +
                   (((lane >> 3) & 1) << 4);

    float acc[4][4][4];
    #pragma unroll
    for (int mt = 0; mt < 4; mt++)
        #pragma unroll
        for (int nt = 0; nt < 4; nt++)
            #pragma unroll
            for (int j = 0; j < 4; j++) acc[mt][nt][j] = 0.f;

    // consumer ring state
    int cst = 0, cph = 0;
    // producer (tid 0) lookahead state: streams stages one ahead of consumer
    int p_cur = bid;   // ticket currently being streamed
    int p_kt  = 1;     // next k-iter to issue within p_cur (stage 0 done in prologue)
    int p_f   = 1;     // global issue index (for empty-bar parity)

    int cur = bid;     // consumer's current tile
    for (;;) {
        const int tile_m = (cur & (NT_M - 1)) * TILE_M;
        const int tile_n = (cur >> 5) * TILE_N;

        for (int kt = 0; kt < NKIT; kt++) {
            // producer: issue next stage (one ahead); steal a new ticket at boundary
            if (tid == 0 && p_cur < NTILES) {
                if (p_kt == NKIT) {
                    p_cur  = atomicAdd(&g_ticket, 1);
                    *s_next = p_cur;   // visible to all after tile-end __syncthreads
                    p_kt = 0;
                }
                if (p_cur < NTILES) {
                    int fs = p_f & 1;
                    if (p_f >= S) MBAR_WAIT(EMPTY_BAR(fs), ((p_f >> 1) - 1) & 1);
                    int fkt = p_kt * KC;
                    int fm  = (p_cur & (NT_M - 1)) * TILE_M;
                    int fn  = (p_cur >> 5) * TILE_N;
                    MBAR_EXPECT_TX(FULL_BAR(fs), STAGE_BYTES);
                    tma2d(sb + A_OFF(fs),           &tmA, fkt,      fm, FULL_BAR(fs));
                    tma2d(sb + A_OFF(fs) + A_CHUNK, &tmA, fkt + 64, fm, FULL_BAR(fs));
                    tma2d(sb + B_OFF(fs),           &tmB, fkt,      fn, FULL_BAR(fs));
                    tma2d(sb + B_OFF(fs) + B_CHUNK, &tmB, fkt + 64, fn, FULL_BAR(fs));
                    p_f++;
                    p_kt++;
                }
            }

            MBAR_WAIT(FULL_BAR(cst), cph);

            #pragma unroll
            for (int ch = 0; ch < 2; ch++) {
                const uint32_t aT = sb + A_OFF(cst) + ch * A_CHUNK;
                const uint32_t bT = sb + B_OFF(cst) + ch * B_CHUNK;
                #pragma unroll
                for (int kk = 0; kk < 4; kk++) {
                    uint32_t a[4][4], b[2][4];
                    #pragma unroll
                    for (int mt = 0; mt < 4; mt++)
                        ldsm4(a[mt], aT + sw128(aRow[mt] + kk * 32));
                    #pragma unroll
                    for (int n2 = 0; n2 < 2; n2++)
                        ldsm4(b[n2], bT + sw128(bRow[n2] + kk * 32));
                    #pragma unroll
                    for (int mt = 0; mt < 4; mt++)
                        #pragma unroll
                        for (int nt = 0; nt < 4; nt++)
                            mma16816(acc[mt][nt], a[mt], &b[nt >> 1][(nt & 1) * 2]);
                }
            }

            if (lane == 0) MBAR_ARRIVE(EMPTY_BAR(cst));
            if (++cst == S) { cst = 0; cph ^= 1; }
        }

        // ---------------- per-tile epilogue (next tile's TMA already in flight) ----
        #pragma unroll
        for (int nt = 0; nt < 4; nt++) {
            const int lc = tile_n + warp_n * 32 + nt * 8 + 2 * (lane & 3);
            const float s0 = __ldg(scales + lc);
            const float s1 = __ldg(scales + lc + 1);
            const float b0 = __ldg(bias + lc);
            const float b1 = __ldg(bias + lc + 1);
            #pragma unroll
            for (int mt = 0; mt < 4; mt++) {
                const int r0 = tile_m + warp_m * 64 + mt * 16 + (lane >> 2);
                float* p0 = out + (size_t)r0 * OUT_F + lc;
                float* p1 = p0 + (size_t)8 * OUT_F;
                float2 v0, v1;
                v0.x = fmaf(acc[mt][nt][0], s0, b0);
                v0.y = fmaf(acc[mt][nt][1], s1, b1);
                v1.x = fmaf(acc[mt][nt][2], s0, b0);
                v1.y = fmaf(acc[mt][nt][3], s1, b1);
                __stcs(reinterpret_cast<float2*>(p0), v0);
                __stcs(reinterpret_cast<float2*>(p1), v1);
            }
        }

        // reset accumulators
        #pragma unroll
        for (int mt = 0; mt < 4; mt++)
            #pragma unroll
            for (int nt = 0; nt < 4; nt++)
                #pragma unroll
                for (int j = 0; j < 4; j++) acc[mt][nt][j] = 0.f;

        __syncthreads();        // orders tid0's *s_next store before everyone's read
        cur = *s_next;
        if (cur >= NTILES) break;
    }
}

// ---------------- host: tensormap + launch ----------------
typedef CUresult (*PFN_tmapenc)(CUtensorMap*, CUtensorMapDataType, cuuint32_t, void*,
                                const cuuint64_t*, const cuuint64_t*, const cuuint32_t*,
                                const cuuint32_t*, CUtensorMapInterleave, CUtensorMapSwizzle,
                                CUtensorMapL2promotion, CUtensorMapFloatOOBfill);

static PFN_tmapenc get_tmap_fn() {
    void* fp = nullptr;
    cudaDriverEntryPointQueryResult qr;
#if CUDART_VERSION >= 12050
    cudaGetDriverEntryPointByVersion("cuTensorMapEncodeTiled", &fp, 12000, cudaEnableDefault, &qr);
#else
    cudaGetDriverEntryPoint("cuTensorMapEncodeTiled", &fp, cudaEnableDefault, &qr);
#endif
    return (PFN_tmapenc)fp;
}

static void make_map(PFN_tmapenc fn, CUtensorMap* m, void* base, uint64_t d0, uint64_t d1,
                     uint32_t b0, uint32_t b1) {
    cuuint64_t dims[2]    = {d0, d1};
    cuuint64_t strides[1] = {d0 * 2};  // bytes (fp16)
    cuuint32_t box[2]     = {b0, b1};
    cuuint32_t es[2]      = {1, 1};
    fn(m, CU_TENSOR_MAP_DATA_TYPE_FLOAT16, 2, base, dims, strides, box, es,
       CU_TENSOR_MAP_INTERLEAVE_NONE, CU_TENSOR_MAP_SWIZZLE_128B,
       CU_TENSOR_MAP_L2_PROMOTION_L2_128B, CU_TENSOR_MAP_FLOAT_OOB_FILL_NONE);
}

extern "C" void kernel_launch(void* const* d_in, const int* in_sizes, int n_in,
                              void* d_out, int out_size) {
    const float* x      = (const float*)d_in[0];
    const int4*  w      = (const int4*)d_in[1];   // int32 weights, 4 per int4
    const float* scales = (const float*)d_in[2];
    const float* bias   = (const float*)d_in[3];
    float*       out    = (float*)d_out;

    void* xp = nullptr;
    void* wp = nullptr;
    cudaGetSymbolAddress(&xp, g_x16);
    cudaGetSymbolAddress(&wp, g_w16);

    int nsm = 148;
    cudaDeviceGetAttribute(&nsm, cudaDevAttrMultiProcessorCount, 0);

    // fused fp16 conversion pre-pass (also resets the work-steal ticket to nsm)
    {
        int n4x = TOKENS * IN_F / 4;
        int n4w = OUT_F * IN_F / 4;
        int tot = n4x + n4w;
        cvt_all_kernel<<<(tot + 255) / 256, 256>>>((const float4*)x, (uint2*)xp, n4x,
                                                   w, (uint2*)wp, n4w, nsm);
    }

    PFN_tmapenc fn = get_tmap_fn();
    CUtensorMap tmA, tmB;
    make_map(fn, &tmA, xp, IN_F, TOKENS, 64, TILE_M);  // A: [K, M], box [64, 256]
    make_map(fn, &tmB, wp, IN_F, OUT_F, 64, TILE_N);   // B: [K, N], box [64, 128]

    cudaFuncSetAttribute(qlin_gemm_kernel, cudaFuncAttributeMaxDynamicSharedMemorySize,
                         SMEM_TOTAL);
    qlin_gemm_kernel<<<nsm, NTHREADS, SMEM_TOTAL>>>(tmA, tmB, scales, bias, out);
}

// round 15
// speedup vs baseline: 1.0323x; 1.0323x over previous
#include <cuda_runtime.h>
#include <cuda.h>
#include <cuda_fp16.h>
#include <cstdint>
#include <cstring>

// ---------------- problem constants ----------------
#define TOKENS 8192
#define IN_F   4096
#define OUT_F  11008

// ---------------- GEMM tiling ----------------
constexpr int TILE_M = 256;            // CTA M
constexpr int TILE_N = 128;            // CTA N
constexpr int KC     = 128;            // K elems per stage (2 x 64-col SW128 chunks)
constexpr int NKIT   = IN_F / KC;      // 32
constexpr int S      = 2;              // pipeline stages (ping-pong)

constexpr int NT_M   = TOKENS / TILE_M;   // 32 (power of two)
constexpr int NT_N   = OUT_F / TILE_N;    // 86
constexpr int NTILES = NT_M * NT_N;       // 2752

// ---------------- SMEM layout ----------------
constexpr int SMEM_TILES   = 1024;                 // 1024-aligned for SW128
constexpr int A_CHUNK      = TILE_M * 128;         // 32768 (64 k-cols)
constexpr int B_CHUNK      = TILE_N * 128;         // 16384
constexpr int A_BYTES      = 2 * A_CHUNK;          // 65536
constexpr int B_BYTES      = 2 * B_CHUNK;          // 32768
constexpr int STAGE_BYTES  = A_BYTES + B_BYTES;    // 98304
constexpr int SMEM_SB      = SMEM_TILES + S * STAGE_BYTES;  // 197632: scales(512)+bias(512)
constexpr int SMEM_TOTAL   = SMEM_SB + 1024;                // 198656

// ---------------- scratch (fp16 copies) + work-steal counter ----------------
__device__ __align__(1024) __half g_x16[(size_t)TOKENS * IN_F];
__device__ __align__(1024) __half g_w16[(size_t)OUT_F * IN_F];
__device__ int g_ticket;

// ---------------- PTX helpers ----------------
__device__ __forceinline__ uint32_t smem_u32(const void* p) {
    uint32_t a;
    asm("{ .reg .u64 t; cvta.to.shared.u64 t, %1; cvt.u32.u64 %0, t; }" : "=r"(a) : "l"(p));
    return a;
}

#define MBAR_INIT(a, c) \
    asm volatile("mbarrier.init.shared.b64 [%0], %1;" :: "r"(a), "r"((uint32_t)(c)) : "memory")

#define MBAR_EXPECT_TX(a, b) \
    asm volatile("mbarrier.arrive.expect_tx.shared.b64 _, [%0], %1;" :: "r"(a), "r"((uint32_t)(b)) : "memory")

#define MBAR_ARRIVE(a) \
    asm volatile("mbarrier.arrive.shared.b64 _, [%0];" :: "r"(a) : "memory")

#define MBAR_WAIT(a, ph) do {                                                          \
    uint32_t _m = (a); uint32_t _p = (uint32_t)(ph); uint32_t _d;                      \
    asm volatile("{\n .reg .pred p;\n"                                                 \
                 " mbarrier.try_wait.parity.acquire.cta.shared::cta.b64 p, [%1], %2;\n" \
                 " selp.b32 %0, 1, 0, p;\n}" : "=r"(_d) : "r"(_m), "r"(_p) : "memory"); \
    if (!_d) {                                                                         \
        asm volatile("{\n .reg .pred P1;\n"                                            \
                     "WL_%=:\n"                                                         \
                     " mbarrier.try_wait.parity.acquire.cta.shared::cta.b64 P1, [%0], %1, 0x989680;\n" \
                     " @P1 bra.uni WD_%=;\n bra.uni WL_%=;\nWD_%=:\n}"                  \
                     :: "r"(_m), "r"(_p) : "memory");                                   \
    }                                                                                   \
} while (0)

// relaxed variant: producer's post-wait accesses are all async-proxy (TMA)
#define MBAR_WAIT_RELAXED(a, ph) do {                                                  \
    uint32_t _m = (a); uint32_t _p = (uint32_t)(ph); uint32_t _d;                      \
    asm volatile("{\n .reg .pred p;\n"                                                 \
                 " mbarrier.try_wait.parity.relaxed.cta.shared::cta.b64 p, [%1], %2, 0x989680;\n" \
                 " selp.b32 %0, 1, 0, p;\n}" : "=r"(_d) : "r"(_m), "r"(_p) : "memory"); \
    if (!_d) {                                                                         \
        asm volatile("{\n .reg .pred P1;\n"                                            \
                     "WL_%=:\n"                                                         \
                     " mbarrier.try_wait.parity.relaxed.cta.shared::cta.b64 P1, [%0], %1, 0x989680;\n" \
                     " @P1 bra.uni WD_%=;\n bra.uni WL_%=;\nWD_%=:\n}"                  \
                     :: "r"(_m), "r"(_p) : "memory");                                   \
    }                                                                                   \
} while (0)

__device__ __forceinline__ void tma2d(uint32_t dst, const CUtensorMap* m, int cx, int cy,
                                      uint32_t bar) {
    asm volatile(
        "cp.async.bulk.tensor.2d.shared::cta.global.tile.mbarrier::complete_tx::bytes "
        "[%0], [%1, {%2, %3}], [%4];"
        :: "r"(dst), "l"(m), "r"(cx), "r"(cy), "r"(bar) : "memory");
}

__device__ __forceinline__ void cp16ca(uint32_t dst, const void* src) {
    asm volatile("cp.async.ca.shared.global [%0], [%1], 16;" :: "r"(dst), "l"(src) : "memory");
}
__device__ __forceinline__ void cp_commit() {
    asm volatile("cp.async.commit_group;" ::: "memory");
}
__device__ __forceinline__ void cp_wait0() {
    asm volatile("cp.async.wait_group 0;" ::: "memory");
}

__device__ __forceinline__ void ldsm4(uint32_t* r, uint32_t addr) {
    asm volatile("ldmatrix.sync.aligned.m8n8.x4.shared.b16 {%0,%1,%2,%3}, [%4];"
                 : "=r"(r[0]), "=r"(r[1]), "=r"(r[2]), "=r"(r[3]) : "r"(addr));
}

__device__ __forceinline__ void mma16816(float* c, const uint32_t* a, const uint32_t* b) {
    asm volatile(
        "mma.sync.aligned.m16n8k16.row.col.f32.f16.f16.f32 "
        "{%0,%1,%2,%3}, {%4,%5,%6,%7}, {%8,%9}, {%0,%1,%2,%3};"
        : "+f"(c[0]), "+f"(c[1]), "+f"(c[2]), "+f"(c[3])
        : "r"(a[0]), "r"(a[1]), "r"(a[2]), "r"(a[3]), "r"(b[0]), "r"(b[1]));
}

// SW128: XOR 16B-column index with (row & 7)
__device__ __forceinline__ uint32_t sw128(uint32_t off) {
    return off ^ ((off >> 3) & 0x70);
}

// ---------------- fused conversion kernel (single launch) ----------------
// x: fp32 -> fp16 ; w: int32 (harness-upcast int8) -> fp16 ; resets ticket
__global__ void __launch_bounds__(256) cvt_all_kernel(const float4* __restrict__ x,
                                                      uint2* __restrict__ ox, int n4x,
                                                      const int4* __restrict__ w,
                                                      uint2* __restrict__ ow, int n4w,
                                                      int ticket0) {
    if (blockIdx.x == 0 && threadIdx.x == 0) g_ticket = ticket0;
    int i = blockIdx.x * blockDim.x + threadIdx.x;
    if (i < n4x) {
        float4 v = x[i];
        __half2 a = __floats2half2_rn(v.x, v.y);
        __half2 b = __floats2half2_rn(v.z, v.w);
        uint2 u;
        memcpy(&u.x, &a, 4);
        memcpy(&u.y, &b, 4);
        ox[i] = u;
    } else {
        int j = i - n4x;
        if (j < n4w) {
            int4 v = w[j];
            __half2 a = __floats2half2_rn((float)v.x, (float)v.y);
            __half2 b = __floats2half2_rn((float)v.z, (float)v.w);
            uint2 u;
            memcpy(&u.x, &a, 4);
            memcpy(&u.y, &b, 4);
            ow[j] = u;
        }
    }
}

// ---------------- main GEMM kernel (persistent + work stealing) ----------------
__global__ void __launch_bounds__(256, 1)
qlin_gemm_kernel(const __grid_constant__ CUtensorMap tmA,
                 const __grid_constant__ CUtensorMap tmB,
                 const float* __restrict__ scales,
                 const float* __restrict__ bias,
                 float* __restrict__ out) {
    extern __shared__ __align__(1024) char smem[];
    const uint32_t sb = smem_u32(smem);
    const int tid  = threadIdx.x;
    const int wid  = tid >> 5;
    const int lane = tid & 31;
    const int warp_m = wid >> 1;     // 0..3  (64 rows each)
    const int warp_n = wid & 1;      // 0..1  (64 cols each)

    const int bid = blockIdx.x;

#define FULL_BAR(s)  (sb + (s) * 16)
#define EMPTY_BAR(s) (sb + (s) * 16 + 8)
#define A_OFF(s)     (SMEM_TILES + (s) * STAGE_BYTES)
#define B_OFF(s)     (A_OFF(s) + A_BYTES)

    int* s_next = reinterpret_cast<int*>(smem + 64);
    float* s_scale = reinterpret_cast<float*>(smem + SMEM_SB);
    float* s_bias  = reinterpret_cast<float*>(smem + SMEM_SB + 512);

    if (tid == 0) {
        #pragma unroll
        for (int s = 0; s < S; s++) {
            MBAR_INIT(FULL_BAR(s), 1);
            MBAR_INIT(EMPTY_BAR(s), 8);
        }
        *s_next = NTILES;  // sentinel until first fetch
    }
    __syncthreads();

    // prologue: issue stage 0 of first (static) tile
    if (tid == 0) {
        int m0 = (bid & (NT_M - 1)) * TILE_M;
        int n0 = (bid >> 5) * TILE_N;
        MBAR_EXPECT_TX(FULL_BAR(0), STAGE_BYTES);
        tma2d(sb + A_OFF(0),           &tmA, 0,  m0, FULL_BAR(0));
        tma2d(sb + A_OFF(0) + A_CHUNK, &tmA, 64, m0, FULL_BAR(0));
        tma2d(sb + B_OFF(0),           &tmB, 0,  n0, FULL_BAR(0));
        tma2d(sb + B_OFF(0) + B_CHUNK, &tmB, 64, n0, FULL_BAR(0));
    }

    // fragment base byte offsets (tile-invariant; chunk-relative, before swizzle)
    uint32_t aRow[4], bRow[4];
    #pragma unroll
    for (int mt = 0; mt < 4; mt++)
        aRow[mt] = (uint32_t)(warp_m * 64 + mt * 16 + (lane & 15)) * 128 +
                   ((lane >> 4) << 4);
    #pragma unroll
    for (int n2 = 0; n2 < 4; n2++)
        bRow[n2] = (uint32_t)(warp_n * 64 + n2 * 16 + (lane & 7) + ((lane >> 4) << 3)) * 128 +
                   (((lane >> 3) & 1) << 4);

    float acc[4][8][4];
    #pragma unroll
    for (int mt = 0; mt < 4; mt++)
        #pragma unroll
        for (int nt = 0; nt < 8; nt++)
            #pragma unroll
            for (int j = 0; j < 4; j++) acc[mt][nt][j] = 0.f;

    // consumer ring state
    int cst = 0, cph = 0;
    // producer (tid 0) lookahead state: streams stages one ahead of consumer
    int p_cur = bid;   // ticket currently being streamed
    int p_kt  = 1;     // next k-iter to issue within p_cur (stage 0 done in prologue)
    int p_f   = 1;     // global issue index (for empty-bar parity)

    int cur = bid;     // consumer's current tile
    for (;;) {
        const int tile_m = (cur & (NT_M - 1)) * TILE_M;
        const int tile_n = (cur >> 5) * TILE_N;

        // stage this tile's scales/bias into smem (lands during the k-loop)
        if (tid < 64) {
            const float* src = (tid < 32) ? (scales + tile_n + (tid & 31) * 4)
                                          : (bias   + tile_n + (tid & 31) * 4);
            uint32_t dst = sb + SMEM_SB + ((tid < 32) ? 0 : 512) + (tid & 31) * 16;
            cp16ca(dst, src);
        }
        cp_commit();

        for (int kt = 0; kt < NKIT; kt++) {
            // producer: issue next stage (one ahead); steal a new ticket at boundary
            if (tid == 0 && p_cur < NTILES) {
                if (p_kt == NKIT) {
                    p_cur  = atomicAdd(&g_ticket, 1);
                    *s_next = p_cur;   // visible to all after tile-end __syncthreads
                    p_kt = 0;
                }
                if (p_cur < NTILES) {
                    int fs = p_f & 1;
                    if (p_f >= S) MBAR_WAIT_RELAXED(EMPTY_BAR(fs), ((p_f >> 1) - 1) & 1);
                    int fkt = p_kt * KC;
                    int fm  = (p_cur & (NT_M - 1)) * TILE_M;
                    int fn  = (p_cur >> 5) * TILE_N;
                    MBAR_EXPECT_TX(FULL_BAR(fs), STAGE_BYTES);
                    tma2d(sb + A_OFF(fs),           &tmA, fkt,      fm, FULL_BAR(fs));
                    tma2d(sb + A_OFF(fs) + A_CHUNK, &tmA, fkt + 64, fm, FULL_BAR(fs));
                    tma2d(sb + B_OFF(fs),           &tmB, fkt,      fn, FULL_BAR(fs));
                    tma2d(sb + B_OFF(fs) + B_CHUNK, &tmB, fkt + 64, fn, FULL_BAR(fs));
                    p_f++;
                    p_kt++;
                }
            }

            MBAR_WAIT(FULL_BAR(cst), cph);

            #pragma unroll
            for (int ch = 0; ch < 2; ch++) {
                const uint32_t aT = sb + A_OFF(cst) + ch * A_CHUNK;
                const uint32_t bT = sb + B_OFF(cst) + ch * B_CHUNK;
                #pragma unroll
                for (int kk = 0; kk < 4; kk++) {
                    uint32_t a[4][4], b[4][4];
                    #pragma unroll
                    for (int mt = 0; mt < 4; mt++)
                        ldsm4(a[mt], aT + sw128(aRow[mt] + kk * 32));
                    #pragma unroll
                    for (int n2 = 0; n2 < 4; n2++)
                        ldsm4(b[n2], bT + sw128(bRow[n2] + kk * 32));
                    #pragma unroll
                    for (int mt = 0; mt < 4; mt++)
                        #pragma unroll
                        for (int nt = 0; nt < 8; nt++)
                            mma16816(acc[mt][nt], a[mt], &b[nt >> 1][(nt & 1) * 2]);
                }
            }

            if (lane == 0) MBAR_ARRIVE(EMPTY_BAR(cst));
            if (++cst == S) { cst = 0; cph ^= 1; }
        }

        // staged scales/bias visible to all threads
        cp_wait0();
        __syncthreads();

        // ---------------- per-tile epilogue (next tile's TMA already in flight) ----
        #pragma unroll
        for (int nt = 0; nt < 8; nt++) {
            const int lcl = warp_n * 64 + nt * 8 + 2 * (lane & 3);
            const int lc  = tile_n + lcl;
            const float s0 = s_scale[lcl];
            const float s1 = s_scale[lcl + 1];
            const float b0 = s_bias[lcl];
            const float b1 = s_bias[lcl + 1];
            #pragma unroll
            for (int mt = 0; mt < 4; mt++) {
                const int r0 = tile_m + warp_m * 64 + mt * 16 + (lane >> 2);
                float* p0 = out + (size_t)r0 * OUT_F + lc;
                float* p1 = p0 + (size_t)8 * OUT_F;
                float2 v0, v1;
                v0.x = fmaf(acc[mt][nt][0], s0, b0);
                v0.y = fmaf(acc[mt][nt][1], s1, b1);
                v1.x = fmaf(acc[mt][nt][2], s0, b0);
                v1.y = fmaf(acc[mt][nt][3], s1, b1);
                __stcs(reinterpret_cast<float2*>(p0), v0);
                __stcs(reinterpret_cast<float2*>(p1), v1);
            }
        }

        // reset accumulators
        #pragma unroll
        for (int mt = 0; mt < 4; mt++)
            #pragma unroll
            for (int nt = 0; nt < 8; nt++)
                #pragma unroll
                for (int j = 0; j < 4; j++) acc[mt][nt][j] = 0.f;

        __syncthreads();        // orders tid0's *s_next store before everyone's read
        cur = *s_next;
        if (cur >= NTILES) break;
    }
}

// ---------------- host: tensormap + launch ----------------
typedef CUresult (*PFN_tmapenc)(CUtensorMap*, CUtensorMapDataType, cuuint32_t, void*,
                                const cuuint64_t*, const cuuint64_t*, const cuuint32_t*,
                                const cuuint32_t*, CUtensorMapInterleave, CUtensorMapSwizzle,
                                CUtensorMapL2promotion, CUtensorMapFloatOOBfill);

static PFN_tmapenc get_tmap_fn() {
    void* fp = nullptr;
    cudaDriverEntryPointQueryResult qr;
#if CUDART_VERSION >= 12050
    cudaGetDriverEntryPointByVersion("cuTensorMapEncodeTiled", &fp, 12000, cudaEnableDefault, &qr);
#else
    cudaGetDriverEntryPoint("cuTensorMapEncodeTiled", &fp, cudaEnableDefault, &qr);
#endif
    return (PFN_tmapenc)fp;
}

static void make_map(PFN_tmapenc fn, CUtensorMap* m, void* base, uint64_t d0, uint64_t d1,
                     uint32_t b0, uint32_t b1) {
    cuuint64_t dims[2]    = {d0, d1};
    cuuint64_t strides[1] = {d0 * 2};  // bytes (fp16)
    cuuint32_t box[2]     = {b0, b1};
    cuuint32_t es[2]      = {1, 1};
    fn(m, CU_TENSOR_MAP_DATA_TYPE_FLOAT16, 2, base, dims, strides, box, es,
       CU_TENSOR_MAP_INTERLEAVE_NONE, CU_TENSOR_MAP_SWIZZLE_128B,
       CU_TENSOR_MAP_L2_PROMOTION_L2_128B, CU_TENSOR_MAP_FLOAT_OOB_FILL_NONE);
}

extern "C" void kernel_launch(void* const* d_in, const int* in_sizes, int n_in,
                              void* d_out, int out_size) {
    const float* x      = (const float*)d_in[0];
    const int4*  w      = (const int4*)d_in[1];   // int32 weights, 4 per int4
    const float* scales = (const float*)d_in[2];
    const float* bias   = (const float*)d_in[3];
    float*       out    = (float*)d_out;

    void* xp = nullptr;
    void* wp = nullptr;
    cudaGetSymbolAddress(&xp, g_x16);
    cudaGetSymbolAddress(&wp, g_w16);

    int nsm = 148;
    cudaDeviceGetAttribute(&nsm, cudaDevAttrMultiProcessorCount, 0);

    // fused fp16 conversion pre-pass (also resets the work-steal ticket to nsm)
    {
        int n4x = TOKENS * IN_F / 4;
        int n4w = OUT_F * IN_F / 4;
        int tot = n4x + n4w;
        cvt_all_kernel<<<(tot + 255) / 256, 256>>>((const float4*)x, (uint2*)xp, n4x,
                                                   w, (uint2*)wp, n4w, nsm);
    }

    PFN_tmapenc fn = get_tmap_fn();
    CUtensorMap tmA, tmB;
    make_map(fn, &tmA, xp, IN_F, TOKENS, 64, TILE_M);  // A: [K, M], box [64, 256]
    make_map(fn, &tmB, wp, IN_F, OUT_F, 64, TILE_N);   // B: [K, N], box [64, 128]

    cudaFuncSetAttribute(qlin_gemm_kernel, cudaFuncAttributeMaxDynamicSharedMemorySize,
                         SMEM_TOTAL);
    qlin_gemm_kernel<<<nsm, 256, SMEM_TOTAL>>>(tmA, tmB, scales, bias, out);
}

// round 16
// speedup vs baseline: 1.0697x; 1.0363x over previous
#include <cuda_runtime.h>
#include <cuda.h>
#include <cuda_fp16.h>
#include <cstdint>
#include <cstring>

// ---------------- problem constants ----------------
#define TOKENS 8192
#define IN_F   4096
#define OUT_F  11008

// ---------------- GEMM tiling ----------------
constexpr int TILE_M = 256;            // CTA M
constexpr int TILE_N = 128;            // CTA N
constexpr int KC     = 128;            // K elems per stage (2 x 64-col SW128 chunks)
constexpr int NKIT   = IN_F / KC;      // 32
constexpr int S      = 2;              // pipeline stages (ping-pong)

constexpr int NT_M   = TOKENS / TILE_M;   // 32 (power of two)
constexpr int NT_N   = OUT_F / TILE_N;    // 86
constexpr int NTILES = NT_M * NT_N;       // 2752

// ---------------- SMEM layout ----------------
// [0 .. 32)  : barriers  full(s)=s*16, empty(s)=s*16+8
// [64]       : next-ticket handoff (int)
// [1024 ..)  : tile stages
constexpr int SMEM_TILES   = 1024;                 // 1024-aligned for SW128
constexpr int A_CHUNK      = TILE_M * 128;         // 32768 (64 k-cols)
constexpr int B_CHUNK      = TILE_N * 128;         // 16384
constexpr int A_BYTES      = 2 * A_CHUNK;          // 65536
constexpr int B_BYTES      = 2 * B_CHUNK;          // 32768
constexpr int STAGE_BYTES  = A_BYTES + B_BYTES;    // 98304
constexpr int SMEM_TOTAL   = SMEM_TILES + S * STAGE_BYTES;  // 197632

// ---------------- scratch (fp16 copies) + work-steal counter ----------------
__device__ __align__(1024) __half g_x16[(size_t)TOKENS * IN_F];
__device__ __align__(1024) __half g_w16[(size_t)OUT_F * IN_F];
__device__ int g_ticket;

// ---------------- PTX helpers ----------------
__device__ __forceinline__ uint32_t smem_u32(const void* p) {
    uint32_t a;
    asm("{ .reg .u64 t; cvta.to.shared.u64 t, %1; cvt.u32.u64 %0, t; }" : "=r"(a) : "l"(p));
    return a;
}

#define MBAR_INIT(a, c) \
    asm volatile("mbarrier.init.shared.b64 [%0], %1;" :: "r"(a), "r"((uint32_t)(c)) : "memory")

#define MBAR_EXPECT_TX(a, b) \
    asm volatile("mbarrier.arrive.expect_tx.shared.b64 _, [%0], %1;" :: "r"(a), "r"((uint32_t)(b)) : "memory")

#define MBAR_ARRIVE(a) \
    asm volatile("mbarrier.arrive.shared.b64 _, [%0];" :: "r"(a) : "memory")

#define MBAR_WAIT(a, ph) do {                                                          \
    uint32_t _m = (a); uint32_t _p = (uint32_t)(ph); uint32_t _d;                      \
    asm volatile("{\n .reg .pred p;\n"                                                 \
                 " mbarrier.try_wait.parity.acquire.cta.shared::cta.b64 p, [%1], %2;\n" \
                 " selp.b32 %0, 1, 0, p;\n}" : "=r"(_d) : "r"(_m), "r"(_p) : "memory"); \
    if (!_d) {                                                                         \
        asm volatile("{\n .reg .pred P1;\n"                                            \
                     "WL_%=:\n"                                                         \
                     " mbarrier.try_wait.parity.acquire.cta.shared::cta.b64 P1, [%0], %1, 0x989680;\n" \
                     " @P1 bra.uni WD_%=;\n bra.uni WL_%=;\nWD_%=:\n}"                  \
                     :: "r"(_m), "r"(_p) : "memory");                                   \
    }                                                                                   \
} while (0)

// relaxed variant: producer-only. Everything tid0 does after this wait is
// async-proxy (TMA), ordered by the TMA mechanism itself — no acquire needed.
#define MBAR_WAIT_RELAXED(a, ph) do {                                                  \
    uint32_t _m = (a); uint32_t _p = (uint32_t)(ph); uint32_t _d;                      \
    asm volatile("{\n .reg .pred p;\n"                                                 \
                 " mbarrier.try_wait.parity.relaxed.cta.shared::cta.b64 p, [%1], %2, 0x989680;\n" \
                 " selp.b32 %0, 1, 0, p;\n}" : "=r"(_d) : "r"(_m), "r"(_p) : "memory"); \
    if (!_d) {                                                                         \
        asm volatile("{\n .reg .pred P1;\n"                                            \
                     "WL_%=:\n"                                                         \
                     " mbarrier.try_wait.parity.relaxed.cta.shared::cta.b64 P1, [%0], %1, 0x989680;\n" \
                     " @P1 bra.uni WD_%=;\n bra.uni WL_%=;\nWD_%=:\n}"                  \
                     :: "r"(_m), "r"(_p) : "memory");                                   \
    }                                                                                   \
} while (0)

__device__ __forceinline__ void tma2d(uint32_t dst, const CUtensorMap* m, int cx, int cy,
                                      uint32_t bar) {
    asm volatile(
        "cp.async.bulk.tensor.2d.shared::cta.global.tile.mbarrier::complete_tx::bytes "
        "[%0], [%1, {%2, %3}], [%4];"
        :: "r"(dst), "l"(m), "r"(cx), "r"(cy), "r"(bar) : "memory");
}

__device__ __forceinline__ void ldsm4(uint32_t* r, uint32_t addr) {
    asm volatile("ldmatrix.sync.aligned.m8n8.x4.shared.b16 {%0,%1,%2,%3}, [%4];"
                 : "=r"(r[0]), "=r"(r[1]), "=r"(r[2]), "=r"(r[3]) : "r"(addr));
}

__device__ __forceinline__ void mma16816(float* c, const uint32_t* a, const uint32_t* b) {
    asm volatile(
        "mma.sync.aligned.m16n8k16.row.col.f32.f16.f16.f32 "
        "{%0,%1,%2,%3}, {%4,%5,%6,%7}, {%8,%9}, {%0,%1,%2,%3};"
        : "+f"(c[0]), "+f"(c[1]), "+f"(c[2]), "+f"(c[3])
        : "r"(a[0]), "r"(a[1]), "r"(a[2]), "r"(a[3]), "r"(b[0]), "r"(b[1]));
}

// SW128: XOR 16B-column index with (row & 7)
__device__ __forceinline__ uint32_t sw128(uint32_t off) {
    return off ^ ((off >> 3) & 0x70);
}

// ---------------- fused conversion kernel (single launch) ----------------
// x: fp32 -> fp16 ; w: int32 (harness-upcast int8) -> fp16 ; resets ticket
__global__ void __launch_bounds__(256) cvt_all_kernel(const float4* __restrict__ x,
                                                      uint2* __restrict__ ox, int n4x,
                                                      const int4* __restrict__ w,
                                                      uint2* __restrict__ ow, int n4w,
                                                      int ticket0) {
    if (blockIdx.x == 0 && threadIdx.x == 0) g_ticket = ticket0;
    int i = blockIdx.x * blockDim.x + threadIdx.x;
    if (i < n4x) {
        float4 v = x[i];
        __half2 a = __floats2half2_rn(v.x, v.y);
        __half2 b = __floats2half2_rn(v.z, v.w);
        uint2 u;
        memcpy(&u.x, &a, 4);
        memcpy(&u.y, &b, 4);
        ox[i] = u;
    } else {
        int j = i - n4x;
        if (j < n4w) {
            int4 v = w[j];
            __half2 a = __floats2half2_rn((float)v.x, (float)v.y);
            __half2 b = __floats2half2_rn((float)v.z, (float)v.w);
            uint2 u;
            memcpy(&u.x, &a, 4);
            memcpy(&u.y, &b, 4);
            ow[j] = u;
        }
    }
}

// ---------------- main GEMM kernel (persistent + work stealing) ----------------
__global__ void __launch_bounds__(256, 1)
qlin_gemm_kernel(const __grid_constant__ CUtensorMap tmA,
                 const __grid_constant__ CUtensorMap tmB,
                 const float* __restrict__ scales,
                 const float* __restrict__ bias,
                 float* __restrict__ out) {
    extern __shared__ __align__(1024) char smem[];
    const uint32_t sb = smem_u32(smem);
    const int tid  = threadIdx.x;
    const int wid  = tid >> 5;
    const int lane = tid & 31;
    const int warp_m = wid >> 1;     // 0..3  (64 rows each)
    const int warp_n = wid & 1;      // 0..1  (64 cols each)

    const int bid = blockIdx.x;

#define FULL_BAR(s)  (sb + (s) * 16)
#define EMPTY_BAR(s) (sb + (s) * 16 + 8)
#define A_OFF(s)     (SMEM_TILES + (s) * STAGE_BYTES)
#define B_OFF(s)     (A_OFF(s) + A_BYTES)

    int* s_next = reinterpret_cast<int*>(smem + 64);

    if (tid == 0) {
        #pragma unroll
        for (int s = 0; s < S; s++) {
            MBAR_INIT(FULL_BAR(s), 1);
            MBAR_INIT(EMPTY_BAR(s), 8);
        }
        *s_next = NTILES;  // sentinel until first fetch
    }
    __syncthreads();

    // prologue: issue stage 0 of first (static) tile
    if (tid == 0) {
        int m0 = (bid & (NT_M - 1)) * TILE_M;
        int n0 = (bid >> 5) * TILE_N;
        MBAR_EXPECT_TX(FULL_BAR(0), STAGE_BYTES);
        tma2d(sb + A_OFF(0),           &tmA, 0,  m0, FULL_BAR(0));
        tma2d(sb + A_OFF(0) + A_CHUNK, &tmA, 64, m0, FULL_BAR(0));
        tma2d(sb + B_OFF(0),           &tmB, 0,  n0, FULL_BAR(0));
        tma2d(sb + B_OFF(0) + B_CHUNK, &tmB, 64, n0, FULL_BAR(0));
    }

    // fragment base byte offsets (tile-invariant; chunk-relative, before swizzle)
    uint32_t aRow[4], bRow[4];
    #pragma unroll
    for (int mt = 0; mt < 4; mt++)
        aRow[mt] = (uint32_t)(warp_m * 64 + mt * 16 + (lane & 15)) * 128 +
                   ((lane >> 4) << 4);
    #pragma unroll
    for (int n2 = 0; n2 < 4; n2++)
        bRow[n2] = (uint32_t)(warp_n * 64 + n2 * 16 + (lane & 7) + ((lane >> 4) << 3)) * 128 +
                   (((lane >> 3) & 1) << 4);

    float acc[4][8][4];
    #pragma unroll
    for (int mt = 0; mt < 4; mt++)
        #pragma unroll
        for (int nt = 0; nt < 8; nt++)
            #pragma unroll
            for (int j = 0; j < 4; j++) acc[mt][nt][j] = 0.f;

    // consumer ring state
    int cst = 0, cph = 0;
    // producer (tid 0) lookahead state: streams stages one ahead of consumer
    int p_cur = bid;   // ticket currently being streamed
    int p_kt  = 1;     // next k-iter to issue within p_cur (stage 0 done in prologue)
    int p_f   = 1;     // global issue index (for empty-bar parity)

    int cur = bid;     // consumer's current tile
    for (;;) {
        const int tile_m = (cur & (NT_M - 1)) * TILE_M;
        const int tile_n = (cur >> 5) * TILE_N;

        for (int kt = 0; kt < NKIT; kt++) {
            // producer: issue next stage (one ahead); steal a new ticket at boundary
            if (tid == 0 && p_cur < NTILES) {
                if (p_kt == NKIT) {
                    p_cur  = atomicAdd(&g_ticket, 1);
                    *s_next = p_cur;   // visible to all after tile-end __syncthreads
                    p_kt = 0;
                }
                if (p_cur < NTILES) {
                    int fs = p_f & 1;
                    if (p_f >= S) MBAR_WAIT_RELAXED(EMPTY_BAR(fs), ((p_f >> 1) - 1) & 1);
                    int fkt = p_kt * KC;
                    int fm  = (p_cur & (NT_M - 1)) * TILE_M;
                    int fn  = (p_cur >> 5) * TILE_N;
                    MBAR_EXPECT_TX(FULL_BAR(fs), STAGE_BYTES);
                    tma2d(sb + A_OFF(fs),           &tmA, fkt,      fm, FULL_BAR(fs));
                    tma2d(sb + A_OFF(fs) + A_CHUNK, &tmA, fkt + 64, fm, FULL_BAR(fs));
                    tma2d(sb + B_OFF(fs),           &tmB, fkt,      fn, FULL_BAR(fs));
                    tma2d(sb + B_OFF(fs) + B_CHUNK, &tmB, fkt + 64, fn, FULL_BAR(fs));
                    p_f++;
                    p_kt++;
                }
            }

            MBAR_WAIT(FULL_BAR(cst), cph);

            #pragma unroll
            for (int ch = 0; ch < 2; ch++) {
                const uint32_t aT = sb + A_OFF(cst) + ch * A_CHUNK;
                const uint32_t bT = sb + B_OFF(cst) + ch * B_CHUNK;
                #pragma unroll
                for (int kk = 0; kk < 4; kk++) {
                    uint32_t a[4][4], b[4][4];
                    #pragma unroll
                    for (int mt = 0; mt < 4; mt++)
                        ldsm4(a[mt], aT + sw128(aRow[mt] + kk * 32));
                    #pragma unroll
                    for (int n2 = 0; n2 < 4; n2++)
                        ldsm4(b[n2], bT + sw128(bRow[n2] + kk * 32));
                    #pragma unroll
                    for (int mt = 0; mt < 4; mt++)
                        #pragma unroll
                        for (int nt = 0; nt < 8; nt++)
                            mma16816(acc[mt][nt], a[mt], &b[nt >> 1][(nt & 1) * 2]);
                }
            }

            if (lane == 0) MBAR_ARRIVE(EMPTY_BAR(cst));
            if (++cst == S) { cst = 0; cph ^= 1; }
        }

        // ---------------- per-tile epilogue (next tile's TMA already in flight) ----
        #pragma unroll
        for (int nt = 0; nt < 8; nt++) {
            const int lc = tile_n + warp_n * 64 + nt * 8 + 2 * (lane & 3);
            const float s0 = __ldg(scales + lc);
            const float s1 = __ldg(scales + lc + 1);
            const float b0 = __ldg(bias + lc);
            const float b1 = __ldg(bias + lc + 1);
            #pragma unroll
            for (int mt = 0; mt < 4; mt++) {
                const int r0 = tile_m + warp_m * 64 + mt * 16 + (lane >> 2);
                float* p0 = out + (size_t)r0 * OUT_F + lc;
                float* p1 = p0 + (size_t)8 * OUT_F;
                float2 v0, v1;
                v0.x = fmaf(acc[mt][nt][0], s0, b0);
                v0.y = fmaf(acc[mt][nt][1], s1, b1);
                v1.x = fmaf(acc[mt][nt][2], s0, b0);
                v1.y = fmaf(acc[mt][nt][3], s1, b1);
                __stcs(reinterpret_cast<float2*>(p0), v0);
                __stcs(reinterpret_cast<float2*>(p1), v1);
            }
        }

        // reset accumulators
        #pragma unroll
        for (int mt = 0; mt < 4; mt++)
            #pragma unroll
            for (int nt = 0; nt < 8; nt++)
                #pragma unroll
                for (int j = 0; j < 4; j++) acc[mt][nt][j] = 0.f;

        __syncthreads();        // orders tid0's *s_next store before everyone's read
        cur = *s_next;
        if (cur >= NTILES) break;
    }
}

// ---------------- host: tensormap + launch ----------------
typedef CUresult (*PFN_tmapenc)(CUtensorMap*, CUtensorMapDataType, cuuint32_t, void*,
                                const cuuint64_t*, const cuuint64_t*, const cuuint32_t*,
                                const cuuint32_t*, CUtensorMapInterleave, CUtensorMapSwizzle,
                                CUtensorMapL2promotion, CUtensorMapFloatOOBfill);

static PFN_tmapenc get_tmap_fn() {
    void* fp = nullptr;
    cudaDriverEntryPointQueryResult qr;
#if CUDART_VERSION >= 12050
    cudaGetDriverEntryPointByVersion("cuTensorMapEncodeTiled", &fp, 12000, cudaEnableDefault, &qr);
#else
    cudaGetDriverEntryPoint("cuTensorMapEncodeTiled", &fp, cudaEnableDefault, &qr);
#endif
    return (PFN_tmapenc)fp;
}

static void make_map(PFN_tmapenc fn, CUtensorMap* m, void* base, uint64_t d0, uint64_t d1,
                     uint32_t b0, uint32_t b1) {
    cuuint64_t dims[2]    = {d0, d1};
    cuuint64_t strides[1] = {d0 * 2};  // bytes (fp16)
    cuuint32_t box[2]     = {b0, b1};
    cuuint32_t es[2]      = {1, 1};
    fn(m, CU_TENSOR_MAP_DATA_TYPE_FLOAT16, 2, base, dims, strides, box, es,
       CU_TENSOR_MAP_INTERLEAVE_NONE, CU_TENSOR_MAP_SWIZZLE_128B,
       CU_TENSOR_MAP_L2_PROMOTION_L2_128B, CU_TENSOR_MAP_FLOAT_OOB_FILL_NONE);
}

extern "C" void kernel_launch(void* const* d_in, const int* in_sizes, int n_in,
                              void* d_out, int out_size) {
    const float* x      = (const float*)d_in[0];
    const int4*  w      = (const int4*)d_in[1];   // int32 weights, 4 per int4
    const float* scales = (const float*)d_in[2];
    const float* bias   = (const float*)d_in[3];
    float*       out    = (float*)d_out;

    void* xp = nullptr;
    void* wp = nullptr;
    cudaGetSymbolAddress(&xp, g_x16);
    cudaGetSymbolAddress(&wp, g_w16);

    int nsm = 148;
    cudaDeviceGetAttribute(&nsm, cudaDevAttrMultiProcessorCount, 0);

    // fused fp16 conversion pre-pass (also resets the work-steal ticket to nsm)
    {
        int n4x = TOKENS * IN_F / 4;
        int n4w = OUT_F * IN_F / 4;
        int tot = n4x + n4w;
        cvt_all_kernel<<<(tot + 255) / 256, 256>>>((const float4*)x, (uint2*)xp, n4x,
                                                   w, (uint2*)wp, n4w, nsm);
    }

    PFN_tmapenc fn = get_tmap_fn();
    CUtensorMap tmA, tmB;
    make_map(fn, &tmA, xp, IN_F, TOKENS, 64, TILE_M);  // A: [K, M], box [64, 256]
    make_map(fn, &tmB, wp, IN_F, OUT_F, 64, TILE_N);   // B: [K, N], box [64, 128]

    cudaFuncSetAttribute(qlin_gemm_kernel, cudaFuncAttributeMaxDynamicSharedMemorySize,
                         SMEM_TOTAL);
    qlin_gemm_kernel<<<nsm, 256, SMEM_TOTAL>>>(tmA, tmB, scales, bias, out);
}

// round 17
// speedup vs baseline: 1.0724x; 1.0025x over previous
#include <cuda_runtime.h>
#include <cuda.h>
#include <cuda_fp16.h>
#include <cstdint>
#include <cstring>

// ---------------- problem constants ----------------
#define TOKENS 8192
#define IN_F   4096
#define OUT_F  11008

// ---------------- GEMM tiling ----------------
constexpr int TILE_M = 256;            // CTA M
constexpr int TILE_N = 128;            // CTA N
constexpr int KC     = 128;            // K elems per stage (2 x 64-col SW128 chunks)
constexpr int NKIT   = IN_F / KC;      // 32
constexpr int S      = 2;              // pipeline stages (ping-pong)

constexpr int NT_M   = TOKENS / TILE_M;   // 32 (power of two)
constexpr int NT_N   = OUT_F / TILE_N;    // 86
constexpr int NTILES = NT_M * NT_N;       // 2752

// ---------------- SMEM layout ----------------
// [0 .. 32)  : barriers  full(s)=s*16, empty(s)=s*16+8
// [64]       : next-ticket handoff (int)
// [1024 ..)  : tile stages
constexpr int SMEM_TILES   = 1024;                 // 1024-aligned for SW128
constexpr int A_CHUNK      = TILE_M * 128;         // 32768 (64 k-cols)
constexpr int B_CHUNK      = TILE_N * 128;         // 16384
constexpr int A_BYTES      = 2 * A_CHUNK;          // 65536
constexpr int B_BYTES      = 2 * B_CHUNK;          // 32768
constexpr int STAGE_BYTES  = A_BYTES + B_BYTES;    // 98304
constexpr int SMEM_TOTAL   = SMEM_TILES + S * STAGE_BYTES;  // 197632

// ---------------- scratch (fp16 copies) + work-steal counter ----------------
__device__ __align__(1024) __half g_x16[(size_t)TOKENS * IN_F];
__device__ __align__(1024) __half g_w16[(size_t)OUT_F * IN_F];
__device__ int g_ticket;

// ---------------- PTX helpers ----------------
__device__ __forceinline__ uint32_t smem_u32(const void* p) {
    uint32_t a;
    asm("{ .reg .u64 t; cvta.to.shared.u64 t, %1; cvt.u32.u64 %0, t; }" : "=r"(a) : "l"(p));
    return a;
}

#define MBAR_INIT(a, c) \
    asm volatile("mbarrier.init.shared.b64 [%0], %1;" :: "r"(a), "r"((uint32_t)(c)) : "memory")

#define MBAR_EXPECT_TX(a, b) \
    asm volatile("mbarrier.arrive.expect_tx.shared.b64 _, [%0], %1;" :: "r"(a), "r"((uint32_t)(b)) : "memory")

#define MBAR_ARRIVE(a) \
    asm volatile("mbarrier.arrive.shared.b64 _, [%0];" :: "r"(a) : "memory")

#define MBAR_WAIT(a, ph) do {                                                          \
    uint32_t _m = (a); uint32_t _p = (uint32_t)(ph); uint32_t _d;                      \
    asm volatile("{\n .reg .pred p;\n"                                                 \
                 " mbarrier.try_wait.parity.acquire.cta.shared::cta.b64 p, [%1], %2;\n" \
                 " selp.b32 %0, 1, 0, p;\n}" : "=r"(_d) : "r"(_m), "r"(_p) : "memory"); \
    if (!_d) {                                                                         \
        asm volatile("{\n .reg .pred P1;\n"                                            \
                     "WL_%=:\n"                                                         \
                     " mbarrier.try_wait.parity.acquire.cta.shared::cta.b64 P1, [%0], %1, 0x989680;\n" \
                     " @P1 bra.uni WD_%=;\n bra.uni WL_%=;\nWD_%=:\n}"                  \
                     :: "r"(_m), "r"(_p) : "memory");                                   \
    }                                                                                   \
} while (0)

// relaxed variant: producer-only. Everything tid0 does after this wait is
// async-proxy (TMA), ordered by the TMA mechanism itself — no acquire needed.
#define MBAR_WAIT_RELAXED(a, ph) do {                                                  \
    uint32_t _m = (a); uint32_t _p = (uint32_t)(ph); uint32_t _d;                      \
    asm volatile("{\n .reg .pred p;\n"                                                 \
                 " mbarrier.try_wait.parity.relaxed.cta.shared::cta.b64 p, [%1], %2, 0x989680;\n" \
                 " selp.b32 %0, 1, 0, p;\n}" : "=r"(_d) : "r"(_m), "r"(_p) : "memory"); \
    if (!_d) {                                                                         \
        asm volatile("{\n .reg .pred P1;\n"                                            \
                     "WL_%=:\n"                                                         \
                     " mbarrier.try_wait.parity.relaxed.cta.shared::cta.b64 P1, [%0], %1, 0x989680;\n" \
                     " @P1 bra.uni WD_%=;\n bra.uni WL_%=;\nWD_%=:\n}"                  \
                     :: "r"(_m), "r"(_p) : "memory");                                   \
    }                                                                                   \
} while (0)

__device__ __forceinline__ void tma2d(uint32_t dst, const CUtensorMap* m, int cx, int cy,
                                      uint32_t bar) {
    asm volatile(
        "cp.async.bulk.tensor.2d.shared::cta.global.tile.mbarrier::complete_tx::bytes "
        "[%0], [%1, {%2, %3}], [%4];"
        :: "r"(dst), "l"(m), "r"(cx), "r"(cy), "r"(bar) : "memory");
}

__device__ __forceinline__ void ldsm4(uint32_t* r, uint32_t addr) {
    asm volatile("ldmatrix.sync.aligned.m8n8.x4.shared.b16 {%0,%1,%2,%3}, [%4];"
                 : "=r"(r[0]), "=r"(r[1]), "=r"(r[2]), "=r"(r[3]) : "r"(addr));
}

__device__ __forceinline__ void mma16816(float* c, const uint32_t* a, const uint32_t* b) {
    asm volatile(
        "mma.sync.aligned.m16n8k16.row.col.f32.f16.f16.f32 "
        "{%0,%1,%2,%3}, {%4,%5,%6,%7}, {%8,%9}, {%0,%1,%2,%3};"
        : "+f"(c[0]), "+f"(c[1]), "+f"(c[2]), "+f"(c[3])
        : "r"(a[0]), "r"(a[1]), "r"(a[2]), "r"(a[3]), "r"(b[0]), "r"(b[1]));
}

// SW128: XOR 16B-column index with (row & 7)
__device__ __forceinline__ uint32_t sw128(uint32_t off) {
    return off ^ ((off >> 3) & 0x70);
}

// ---------------- fused conversion kernel (single launch, MLP=2) ----------------
// x: fp32 -> fp16 ; w: int32 (harness-upcast int8) -> fp16 ; resets ticket.
// Each thread handles chunks j and j+half; both 16B loads issued before either
// convert so two loads are in flight per thread (MLP=2).
__device__ __forceinline__ uint2 cvt_x_chunk(uint4 r) {
    float4 v;
    memcpy(&v, &r, 16);
    __half2 a = __floats2half2_rn(v.x, v.y);
    __half2 b = __floats2half2_rn(v.z, v.w);
    uint2 u;
    memcpy(&u.x, &a, 4);
    memcpy(&u.y, &b, 4);
    return u;
}
__device__ __forceinline__ uint2 cvt_w_chunk(uint4 r) {
    int4 v;
    memcpy(&v, &r, 16);
    __half2 a = __floats2half2_rn((float)v.x, (float)v.y);
    __half2 b = __floats2half2_rn((float)v.z, (float)v.w);
    uint2 u;
    memcpy(&u.x, &a, 4);
    memcpy(&u.y, &b, 4);
    return u;
}

__global__ void __launch_bounds__(256) cvt_all_kernel(const uint4* __restrict__ x,
                                                      uint2* __restrict__ ox, int n4x,
                                                      const uint4* __restrict__ w,
                                                      uint2* __restrict__ ow, int n4w,
                                                      int half, int ticket0) {
    if (blockIdx.x == 0 && threadIdx.x == 0) g_ticket = ticket0;
    const int i = blockIdx.x * blockDim.x + threadIdx.x;
    if (i >= half) return;
    const int total = n4x + n4w;
    const int j0 = i;
    const int j1 = i + half;
    const bool x0 = (j0 < n4x);
    const bool x1 = (j1 < n4x);

    // both loads issued back-to-back -> 2 outstanding 16B loads per thread
    const uint4* s0 = x0 ? (x + j0) : (w + (j0 - n4x));
    uint4 r0 = *s0;
    uint4 r1;
    const bool has1 = (j1 < total);
    if (has1) {
        const uint4* s1 = x1 ? (x + j1) : (w + (j1 - n4x));
        r1 = *s1;
    }

    uint2 u0 = x0 ? cvt_x_chunk(r0) : cvt_w_chunk(r0);
    if (x0) ox[j0] = u0; else ow[j0 - n4x] = u0;

    if (has1) {
        uint2 u1 = x1 ? cvt_x_chunk(r1) : cvt_w_chunk(r1);
        if (x1) ox[j1] = u1; else ow[j1 - n4x] = u1;
    }
}

// ---------------- main GEMM kernel (persistent + work stealing) ----------------
__global__ void __launch_bounds__(256, 1)
qlin_gemm_kernel(const __grid_constant__ CUtensorMap tmA,
                 const __grid_constant__ CUtensorMap tmB,
                 const float* __restrict__ scales,
                 const float* __restrict__ bias,
                 float* __restrict__ out) {
    extern __shared__ __align__(1024) char smem[];
    const uint32_t sb = smem_u32(smem);
    const int tid  = threadIdx.x;
    const int wid  = tid >> 5;
    const int lane = tid & 31;
    const int warp_m = wid >> 1;     // 0..3  (64 rows each)
    const int warp_n = wid & 1;      // 0..1  (64 cols each)

    const int bid = blockIdx.x;

#define FULL_BAR(s)  (sb + (s) * 16)
#define EMPTY_BAR(s) (sb + (s) * 16 + 8)
#define A_OFF(s)     (SMEM_TILES + (s) * STAGE_BYTES)
#define B_OFF(s)     (A_OFF(s) + A_BYTES)

    int* s_next = reinterpret_cast<int*>(smem + 64);

    if (tid == 0) {
        #pragma unroll
        for (int s = 0; s < S; s++) {
            MBAR_INIT(FULL_BAR(s), 1);
            MBAR_INIT(EMPTY_BAR(s), 8);
        }
        *s_next = NTILES;  // sentinel until first fetch
    }
    __syncthreads();

    // prologue: issue stage 0 of first (static) tile
    if (tid == 0) {
        int m0 = (bid & (NT_M - 1)) * TILE_M;
        int n0 = (bid >> 5) * TILE_N;
        MBAR_EXPECT_TX(FULL_BAR(0), STAGE_BYTES);
        tma2d(sb + A_OFF(0),           &tmA, 0,  m0, FULL_BAR(0));
        tma2d(sb + A_OFF(0) + A_CHUNK, &tmA, 64, m0, FULL_BAR(0));
        tma2d(sb + B_OFF(0),           &tmB, 0,  n0, FULL_BAR(0));
        tma2d(sb + B_OFF(0) + B_CHUNK, &tmB, 64, n0, FULL_BAR(0));
    }

    // fragment base byte offsets (tile-invariant; chunk-relative, before swizzle)
    uint32_t aRow[4], bRow[4];
    #pragma unroll
    for (int mt = 0; mt < 4; mt++)
        aRow[mt] = (uint32_t)(warp_m * 64 + mt * 16 + (lane & 15)) * 128 +
                   ((lane >> 4) << 4);
    #pragma unroll
    for (int n2 = 0; n2 < 4; n2++)
        bRow[n2] = (uint32_t)(warp_n * 64 + n2 * 16 + (lane & 7) + ((lane >> 4) << 3)) * 128 +
                   (((lane >> 3) & 1) << 4);

    float acc[4][8][4];
    #pragma unroll
    for (int mt = 0; mt < 4; mt++)
        #pragma unroll
        for (int nt = 0; nt < 8; nt++)
            #pragma unroll
            for (int j = 0; j < 4; j++) acc[mt][nt][j] = 0.f;

    // consumer ring state
    int cst = 0, cph = 0;
    // producer (tid 0) lookahead state: streams stages one ahead of consumer
    int p_cur = bid;   // ticket currently being streamed
    int p_kt  = 1;     // next k-iter to issue within p_cur (stage 0 done in prologue)
    int p_f   = 1;     // global issue index (for empty-bar parity)

    int cur = bid;     // consumer's current tile
    for (;;) {
        const int tile_m = (cur & (NT_M - 1)) * TILE_M;
        const int tile_n = (cur >> 5) * TILE_N;

        for (int kt = 0; kt < NKIT; kt++) {
            // producer: issue next stage (one ahead); steal a new ticket at boundary
            if (tid == 0 && p_cur < NTILES) {
                if (p_kt == NKIT) {
                    p_cur  = atomicAdd(&g_ticket, 1);
                    *s_next = p_cur;   // visible to all after tile-end __syncthreads
                    p_kt = 0;
                }
                if (p_cur < NTILES) {
                    int fs = p_f & 1;
                    if (p_f >= S) MBAR_WAIT_RELAXED(EMPTY_BAR(fs), ((p_f >> 1) - 1) & 1);
                    int fkt = p_kt * KC;
                    int fm  = (p_cur & (NT_M - 1)) * TILE_M;
                    int fn  = (p_cur >> 5) * TILE_N;
                    MBAR_EXPECT_TX(FULL_BAR(fs), STAGE_BYTES);
                    tma2d(sb + A_OFF(fs),           &tmA, fkt,      fm, FULL_BAR(fs));
                    tma2d(sb + A_OFF(fs) + A_CHUNK, &tmA, fkt + 64, fm, FULL_BAR(fs));
                    tma2d(sb + B_OFF(fs),           &tmB, fkt,      fn, FULL_BAR(fs));
                    tma2d(sb + B_OFF(fs) + B_CHUNK, &tmB, fkt + 64, fn, FULL_BAR(fs));
                    p_f++;
                    p_kt++;
                }
            }

            MBAR_WAIT(FULL_BAR(cst), cph);

            #pragma unroll
            for (int ch = 0; ch < 2; ch++) {
                const uint32_t aT = sb + A_OFF(cst) + ch * A_CHUNK;
                const uint32_t bT = sb + B_OFF(cst) + ch * B_CHUNK;
                #pragma unroll
                for (int kk = 0; kk < 4; kk++) {
                    uint32_t a[4][4], b[4][4];
                    #pragma unroll
                    for (int mt = 0; mt < 4; mt++)
                        ldsm4(a[mt], aT + sw128(aRow[mt] + kk * 32));
                    #pragma unroll
                    for (int n2 = 0; n2 < 4; n2++)
                        ldsm4(b[n2], bT + sw128(bRow[n2] + kk * 32));
                    #pragma unroll
                    for (int mt = 0; mt < 4; mt++)
                        #pragma unroll
                        for (int nt = 0; nt < 8; nt++)
                            mma16816(acc[mt][nt], a[mt], &b[nt >> 1][(nt & 1) * 2]);
                }
            }

            if (lane == 0) MBAR_ARRIVE(EMPTY_BAR(cst));
            if (++cst == S) { cst = 0; cph ^= 1; }
        }

        // ---------------- per-tile epilogue (next tile's TMA already in flight) ----
        #pragma unroll
        for (int nt = 0; nt < 8; nt++) {
            const int lc = tile_n + warp_n * 64 + nt * 8 + 2 * (lane & 3);
            const float s0 = __ldg(scales + lc);
            const float s1 = __ldg(scales + lc + 1);
            const float b0 = __ldg(bias + lc);
            const float b1 = __ldg(bias + lc + 1);
            #pragma unroll
            for (int mt = 0; mt < 4; mt++) {
                const int r0 = tile_m + warp_m * 64 + mt * 16 + (lane >> 2);
                float* p0 = out + (size_t)r0 * OUT_F + lc;
                float* p1 = p0 + (size_t)8 * OUT_F;
                float2 v0, v1;
                v0.x = fmaf(acc[mt][nt][0], s0, b0);
                v0.y = fmaf(acc[mt][nt][1], s1, b1);
                v1.x = fmaf(acc[mt][nt][2], s0, b0);
                v1.y = fmaf(acc[mt][nt][3], s1, b1);
                __stcs(reinterpret_cast<float2*>(p0), v0);
                __stcs(reinterpret_cast<float2*>(p1), v1);
            }
        }

        // reset accumulators
        #pragma unroll
        for (int mt = 0; mt < 4; mt++)
            #pragma unroll
            for (int nt = 0; nt < 8; nt++)
                #pragma unroll
                for (int j = 0; j < 4; j++) acc[mt][nt][j] = 0.f;

        __syncthreads();        // orders tid0's *s_next store before everyone's read
        cur = *s_next;
        if (cur >= NTILES) break;
    }
}

// ---------------- host: tensormap + launch ----------------
typedef CUresult (*PFN_tmapenc)(CUtensorMap*, CUtensorMapDataType, cuuint32_t, void*,
                                const cuuint64_t*, const cuuint64_t*, const cuuint32_t*,
                                const cuuint32_t*, CUtensorMapInterleave, CUtensorMapSwizzle,
                                CUtensorMapL2promotion, CUtensorMapFloatOOBfill);

static PFN_tmapenc get_tmap_fn() {
    void* fp = nullptr;
    cudaDriverEntryPointQueryResult qr;
#if CUDART_VERSION >= 12050
    cudaGetDriverEntryPointByVersion("cuTensorMapEncodeTiled", &fp, 12000, cudaEnableDefault, &qr);
#else
    cudaGetDriverEntryPoint("cuTensorMapEncodeTiled", &fp, cudaEnableDefault, &qr);
#endif
    return (PFN_tmapenc)fp;
}

static void make_map(PFN_tmapenc fn, CUtensorMap* m, void* base, uint64_t d0, uint64_t d1,
                     uint32_t b0, uint32_t b1) {
    cuuint64_t dims[2]    = {d0, d1};
    cuuint64_t strides[1] = {d0 * 2};  // bytes (fp16)
    cuuint32_t box[2]     = {b0, b1};
    cuuint32_t es[2]      = {1, 1};
    fn(m, CU_TENSOR_MAP_DATA_TYPE_FLOAT16, 2, base, dims, strides, box, es,
       CU_TENSOR_MAP_INTERLEAVE_NONE, CU_TENSOR_MAP_SWIZZLE_128B,
       CU_TENSOR_MAP_L2_PROMOTION_L2_128B, CU_TENSOR_MAP_FLOAT_OOB_FILL_NONE);
}

extern "C" void kernel_launch(void* const* d_in, const int* in_sizes, int n_in,
                              void* d_out, int out_size) {
    const float* x      = (const float*)d_in[0];
    const int*   w      = (const int*)d_in[1];    // int32 weights
    const float* scales = (const float*)d_in[2];
    const float* bias   = (const float*)d_in[3];
    float*       out    = (float*)d_out;

    void* xp = nullptr;
    void* wp = nullptr;
    cudaGetSymbolAddress(&xp, g_x16);
    cudaGetSymbolAddress(&wp, g_w16);

    int nsm = 148;
    cudaDeviceGetAttribute(&nsm, cudaDevAttrMultiProcessorCount, 0);

    // fused fp16 conversion pre-pass, MLP=2 (also resets work-steal ticket to nsm)
    {
        int n4x  = TOKENS * IN_F / 4;   // 8,388,608
        int n4w  = OUT_F * IN_F / 4;    // 11,272,192
        int tot  = n4x + n4w;           // 19,660,800
        int half = (tot + 1) / 2;       // 9,830,400
        cvt_all_kernel<<<(half + 255) / 256, 256>>>((const uint4*)x, (uint2*)xp, n4x,
                                                    (const uint4*)w, (uint2*)wp, n4w,
                                                    half, nsm);
    }

    PFN_tmapenc fn = get_tmap_fn();
    CUtensorMap tmA, tmB;
    make_map(fn, &tmA, xp, IN_F, TOKENS, 64, TILE_M);  // A: [K, M], box [64, 256]
    make_map(fn, &tmB, wp, IN_F, OUT_F, 64, TILE_N);   // B: [K, N], box [64, 128]

    cudaFuncSetAttribute(qlin_gemm_kernel, cudaFuncAttributeMaxDynamicSharedMemorySize,
                         SMEM_TOTAL);
    qlin_gemm_kernel<<<nsm, 256, SMEM_TOTAL>>>(tmA, tmB, scales, bias, out);
}